// round 2
// baseline (speedup 1.0000x reference)
#include <cuda_runtime.h>
#include <cuda_bf16.h>

// Conv2d 3x3, stride 1, pad 1.
// x: [256, 224, 224] fp32, w: [256, 256, 3, 3] fp32, out: [256, 224, 224] fp32
//
// Round 2: packed fp32x2 FMA (fma.rn.f32x2 -> FFMA2), pairing along co so
// weight pairs load directly as 64-bit smem reads. 2x fp32 throughput vs
// scalar FFMA (which is rt_SMSP=2 on sm_103a).

#define C_IN   256
#define C_OUT  256
#define H_IMG  224
#define W_IMG  224

#define OW_T   32   // output tile width
#define OH_T   8    // output tile height
#define CO_T   32   // output channels per block
#define CI_C   4    // input channels per smem chunk

#define IW_T   34   // input patch width  (OW_T + 2)
#define IH_T   10   // input patch height (OH_T + 2)
#define IW_PAD 36   // padded row stride (multiple of 4 floats)

// Transposed weights: [ci][tap(9)][co]  => 256*9*256 floats = 2.36 MB
__device__ float g_wt[C_IN * 9 * C_OUT];

__global__ void wt_transpose_kernel(const float* __restrict__ w) {
    int idx = blockIdx.x * blockDim.x + threadIdx.x;
    if (idx >= C_OUT * C_IN * 9) return;
    int co  = idx / (C_IN * 9);
    int rem = idx % (C_IN * 9);
    int ci  = rem / 9;
    int tap = rem % 9;
    g_wt[(ci * 9 + tap) * C_OUT + co] = w[idx];
}

__device__ __forceinline__ unsigned long long fma2(unsigned long long a,
                                                   unsigned long long b,
                                                   unsigned long long c) {
    unsigned long long d;
    asm("fma.rn.f32x2 %0, %1, %2, %3;" : "=l"(d) : "l"(a), "l"(b), "l"(c));
    return d;
}

__device__ __forceinline__ unsigned long long pack2(float lo, float hi) {
    unsigned long long d;
    asm("mov.b64 %0, {%1, %2};" : "=l"(d) : "f"(lo), "f"(hi));
    return d;
}

__global__ __launch_bounds__(256, 2)
void conv3x3_kernel(const float* __restrict__ x, float* __restrict__ out) {
    __shared__ __align__(16) float s_in[CI_C][IH_T][IW_PAD];  // 5.76 KB
    __shared__ __align__(16) float s_w[CI_C][9][CO_T];        // 4.61 KB

    const int tid = threadIdx.x;
    const int x0b = blockIdx.x * OW_T;
    const int y0b = blockIdx.y * OH_T;
    const int co0 = blockIdx.z * CO_T;

    const int tx  = tid & 7;            // 8 x-groups (4 px each)
    const int ty  = (tid >> 3) & 7;     // 8 rows
    const int tz  = tid >> 6;           // 4 co-groups (8 co each)
    const int tx4 = tx * 4;
    const int tz8 = tz * 8;

    // acc2[p][j2]: pixel p (0..3), co-pair j2 (0..3) => 8 co, 4 px per thread
    unsigned long long acc2[4][4];
#pragma unroll
    for (int p = 0; p < 4; ++p)
#pragma unroll
        for (int j2 = 0; j2 < 4; ++j2) acc2[p][j2] = 0ull;

    for (int ci0 = 0; ci0 < C_IN; ci0 += CI_C) {
        __syncthreads();   // protect smem from previous iteration's readers

        // ---- stage input patch: CI_C planes of 34x10, zero-padded at borders
        for (int i = tid; i < CI_C * IH_T * IW_T; i += 256) {
            int c  = i / (IH_T * IW_T);
            int r  = i % (IH_T * IW_T);
            int yy = r / IW_T;
            int xx = r % IW_T;
            int gy = y0b + yy - 1;
            int gx = x0b + xx - 1;
            float v = 0.0f;
            if ((unsigned)gy < (unsigned)H_IMG && (unsigned)gx < (unsigned)W_IMG)
                v = x[((ci0 + c) * H_IMG + gy) * W_IMG + gx];
            s_in[c][yy][xx] = v;
        }
        // ---- stage weights: CI_C * 9 * 32 contiguous-co rows
        for (int i = tid; i < CI_C * 9 * CO_T; i += 256) {
            int c = i / (9 * CO_T);
            int r = i % (9 * CO_T);
            int t = r / CO_T;
            int j = r % CO_T;
            s_w[c][t][j] = g_wt[((ci0 + c) * 9 + t) * C_OUT + co0 + j];
        }
        __syncthreads();

        // ---- compute: packed f32x2 FMA
#pragma unroll
        for (int c = 0; c < CI_C; ++c) {
#pragma unroll
            for (int ky = 0; ky < 3; ++ky) {
                const float* ir = &s_in[c][ty + ky][tx4];
                float4 ia = *(const float4*)(ir);
                float2 ib = *(const float2*)(ir + 4);
                // 6 inputs, each broadcast-packed into both f32x2 lanes
                unsigned long long iv2[6];
                iv2[0] = pack2(ia.x, ia.x);
                iv2[1] = pack2(ia.y, ia.y);
                iv2[2] = pack2(ia.z, ia.z);
                iv2[3] = pack2(ia.w, ia.w);
                iv2[4] = pack2(ib.x, ib.x);
                iv2[5] = pack2(ib.y, ib.y);
#pragma unroll
                for (int kx = 0; kx < 3; ++kx) {
                    // 8 co weights = 4 co-pairs, loaded directly as 64-bit pairs
                    const ulonglong2* wp =
                        (const ulonglong2*)&s_w[c][ky * 3 + kx][tz8];
                    ulonglong2 wA = wp[0];
                    ulonglong2 wB = wp[1];
                    unsigned long long wpair[4] = {wA.x, wA.y, wB.x, wB.y};
#pragma unroll
                    for (int p = 0; p < 4; ++p) {
#pragma unroll
                        for (int j2 = 0; j2 < 4; ++j2) {
                            acc2[p][j2] = fma2(wpair[j2], iv2[kx + p], acc2[p][j2]);
                        }
                    }
                }
            }
        }
    }

    // ---- epilogue: unpack and write 4px x 8co per thread, vectorized
    const int oy = y0b + ty;
    const int ox = x0b + tx4;
#pragma unroll
    for (int j2 = 0; j2 < 4; ++j2) {
        float olo[4], ohi[4];
#pragma unroll
        for (int p = 0; p < 4; ++p) {
            asm("mov.b64 {%0, %1}, %2;"
                : "=f"(olo[p]), "=f"(ohi[p]) : "l"(acc2[p][j2]));
        }
        int co = co0 + tz8 + j2 * 2;
        *(float4*)&out[(co * H_IMG + oy) * W_IMG + ox] =
            make_float4(olo[0], olo[1], olo[2], olo[3]);
        *(float4*)&out[((co + 1) * H_IMG + oy) * W_IMG + ox] =
            make_float4(ohi[0], ohi[1], ohi[2], ohi[3]);
    }
}

extern "C" void kernel_launch(void* const* d_in, const int* in_sizes, int n_in,
                              void* d_out, int out_size) {
    const float* x = (const float*)d_in[0];   // [1,256,224,224]
    const float* w = (const float*)d_in[1];   // [256,256,3,3]
    float* out = (float*)d_out;               // [256,224,224]

    (void)in_sizes; (void)n_in; (void)out_size;

    int nw = C_OUT * C_IN * 9;
    wt_transpose_kernel<<<(nw + 255) / 256, 256>>>(w);

    dim3 grid(W_IMG / OW_T, H_IMG / OH_T, C_OUT / CO_T);   // 7 x 28 x 8
    conv3x3_kernel<<<grid, 256>>>(x, out);
}

// round 4
// speedup vs baseline: 2.8852x; 2.8852x over previous
#include <cuda_runtime.h>
#include <cuda_bf16.h>
#include <cstdint>

// Conv2d 3x3 s1 p1: x[256,224,224] f32, w[256,256,3,3] f32 -> out[256,224,224] f32
// Baseline-PTX tensor-core implicit GEMM (mma.sync m16n8k16 bf16, f32 accum).
// 3-pass bf16 hi/lo split: w*x ~= wh*xh + wh*xl + wl*xh  (rel err ~1e-5).
// Prep kernels write kx-pre-shifted zero-padded x copies and tile-ready weights
// so the conv mainloop is pure aligned cp.async + ldmatrix + mma.

#define H 224
#define W 224
#define C 256

// x copies: [kx(3)][ci(256)][yy(226)][x(224)] bf16, value = xpad[ci][yy-1][x+kx-1]
__device__ __align__(16) __nv_bfloat16 g_xh[3ull * C * 226 * 224];
__device__ __align__(16) __nv_bfloat16 g_xl[3ull * C * 226 * 224];
// weights: [s(2)][coh(2)][ky(3)][kc(24)][co(128)][j(32)] bf16, k = kc*32+j = kx*256+ci
#define WELEMS 589824  // 2*3*24*128*32
__device__ __align__(16) __nv_bfloat16 g_w[2ull * WELEMS];

// ---------------- prep ----------------
__global__ void prep_w_kernel(const float* __restrict__ w) {
    int i = blockIdx.x * blockDim.x + threadIdx.x;
    if (i >= WELEMS) return;
    int j    = i & 31;
    int co   = (i >> 5) & 127;
    int hi12 = i >> 12;
    int kc   = hi12 % 24;
    int t    = hi12 / 24;
    int ky   = t % 3;
    int coh  = t / 3;
    int k  = kc * 32 + j;
    int kx = k >> 8;
    int ci = k & 255;
    float v = w[(((coh * 128 + co) * C + ci) * 3 + ky) * 3 + kx];
    __nv_bfloat16 hi = __float2bfloat16(v);
    __nv_bfloat16 lo = __float2bfloat16(v - __bfloat162float(hi));
    g_w[i] = hi;
    g_w[WELEMS + i] = lo;
}

__global__ void prep_x_kernel(const float* __restrict__ x) {
    int yy = blockIdx.x;    // 0..225
    int ci = blockIdx.y;    // 0..255
    int xi = threadIdx.x;   // 0..223
    int ys = yy - 1;
#pragma unroll
    for (int kx = 0; kx < 3; ++kx) {
        int xs = xi + kx - 1;
        float v = 0.0f;
        if ((unsigned)ys < 224u && (unsigned)xs < 224u)
            v = x[(ci * H + ys) * W + xs];
        __nv_bfloat16 hi = __float2bfloat16(v);
        __nv_bfloat16 lo = __float2bfloat16(v - __bfloat162float(hi));
        size_t o = (((size_t)kx * C + ci) * 226 + yy) * 224 + xi;
        g_xh[o] = hi;
        g_xl[o] = lo;
    }
}

// ---------------- conv mainloop ----------------
__device__ __forceinline__ uint32_t smem_u32(const void* p) {
    uint32_t a;
    asm("{ .reg .u64 t; cvta.to.shared.u64 t, %1; cvt.u32.u64 %0, t; }" : "=r"(a) : "l"(p));
    return a;
}
__device__ __forceinline__ void cp16(uint32_t dst, const void* src) {
    asm volatile("cp.async.cg.shared.global [%0], [%1], 16;" :: "r"(dst), "l"(src) : "memory");
}
__device__ __forceinline__ void cp_commit() {
    asm volatile("cp.async.commit_group;" ::: "memory");
}
__device__ __forceinline__ void ldsm_x4(uint32_t* r, uint32_t a) {
    asm volatile("ldmatrix.sync.aligned.m8n8.x4.shared.b16 {%0,%1,%2,%3}, [%4];"
                 : "=r"(r[0]), "=r"(r[1]), "=r"(r[2]), "=r"(r[3]) : "r"(a));
}
__device__ __forceinline__ void ldsm_x2t(uint32_t* r, uint32_t a) {
    asm volatile("ldmatrix.sync.aligned.m8n8.x2.trans.shared.b16 {%0,%1}, [%2];"
                 : "=r"(r[0]), "=r"(r[1]) : "r"(a));
}
__device__ __forceinline__ void mma16816(float* d, const uint32_t* a, const uint32_t* b) {
    asm volatile(
        "mma.sync.aligned.m16n8k16.row.col.f32.bf16.bf16.f32 "
        "{%0,%1,%2,%3}, {%4,%5,%6,%7}, {%8,%9}, {%0,%1,%2,%3};"
        : "+f"(d[0]), "+f"(d[1]), "+f"(d[2]), "+f"(d[3])
        : "r"(a[0]), "r"(a[1]), "r"(a[2]), "r"(a[3]), "r"(b[0]), "r"(b[1]));
}

#define A_BYTES 10240           // 128 rows * 80B (64 used)
#define B_BYTES 7680            // 32 rows * 240B (224 used)
#define STAGE_BYTES (A_BYTES + B_BYTES)
#define NSTAGE 216              // 3 pass * 3 ky * 24 kc

__device__ __forceinline__ void load_stage(int idx, uint32_t sbase, int tid,
                                           int coh, int xh, int y) {
    int pass = idx / 72;
    int r = idx - pass * 72;
    int ky = r / 24;
    int kc = r - ky * 24;
    const __nv_bfloat16* wsrc = g_w + (pass == 2 ? WELEMS : 0)
                              + (((size_t)(coh * 3 + ky) * 24 + kc) << 12);
    const __nv_bfloat16* xarr = (pass == 1) ? g_xl : g_xh;
    int kx  = kc >> 3;
    int cib = (kc & 7) * 32;
    // A: 512 x 16B, contiguous src
    uint32_t abase = sbase;
#pragma unroll
    for (int v = tid; v < 512; v += 256) {
        cp16(abase + (v >> 2) * 80 + (v & 3) * 16, (const char*)wsrc + v * 16);
    }
    // B: 448 x 16B
    uint32_t bbase = sbase + A_BYTES;
    for (int v = tid; v < 448; v += 256) {
        int row = v / 14;
        int cv  = v - row * 14;
        size_t se = (((size_t)(kx * C + cib + row)) * 226 + (y + ky)) * 224 + xh * 112;
        cp16(bbase + row * 240 + cv * 16, (const char*)xarr + se * 2 + cv * 16);
    }
}

__global__ __launch_bounds__(256, 2) void conv_mma_kernel(float* __restrict__ out) {
    __shared__ __align__(16) unsigned char smbuf[2 * STAGE_BYTES];   // 35840 B
    const uint32_t sb = smem_u32(smbuf);
    const int tid  = threadIdx.x;
    const int lane = tid & 31;
    const int wid  = tid >> 5;
    const int wm   = wid & 3;     // warp M index (co)
    const int wn   = wid >> 2;    // warp N index (px)
    const int xh   = blockIdx.x & 1;
    const int coh  = blockIdx.x >> 1;
    const int y    = blockIdx.y;

    float acc[2][7][4];
#pragma unroll
    for (int m = 0; m < 2; ++m)
#pragma unroll
        for (int n = 0; n < 7; ++n)
#pragma unroll
            for (int q = 0; q < 4; ++q) acc[m][n][q] = 0.0f;

    load_stage(0, sb, tid, coh, xh, y);
    cp_commit();

    for (int i = 0; i < NSTAGE; ++i) {
        if (i + 1 < NSTAGE) {
            load_stage(i + 1, sb + ((i + 1) & 1) * STAGE_BYTES, tid, coh, xh, y);
            cp_commit();
            asm volatile("cp.async.wait_group 1;" ::: "memory");
        } else {
            asm volatile("cp.async.wait_group 0;" ::: "memory");
        }
        __syncthreads();

        const uint32_t As = sb + (i & 1) * STAGE_BYTES;
        const uint32_t Bs = As + A_BYTES;
        // fragment addresses
        uint32_t aA[2], aB[7];
#pragma unroll
        for (int m = 0; m < 2; ++m)
            aA[m] = As + (wm * 32 + m * 16 + (lane & 15)) * 80 + (lane >> 4) * 16;
#pragma unroll
        for (int n = 0; n < 7; ++n)
            aB[n] = Bs + (lane & 15) * 240 + wn * 112 + n * 16;

#pragma unroll
        for (int ks = 0; ks < 2; ++ks) {
            uint32_t a[2][4], b[7][2];
#pragma unroll
            for (int m = 0; m < 2; ++m) ldsm_x4(a[m], aA[m] + ks * 32);
#pragma unroll
            for (int n = 0; n < 7; ++n) ldsm_x2t(b[n], aB[n] + ks * 16 * 240);
#pragma unroll
            for (int m = 0; m < 2; ++m)
#pragma unroll
                for (int n = 0; n < 7; ++n) mma16816(acc[m][n], a[m], b[n]);
        }
        __syncthreads();
    }

    // epilogue: write D tiles (f32)
    const int rq = lane >> 2;
    const int cq = (lane & 3) * 2;
#pragma unroll
    for (int m = 0; m < 2; ++m) {
#pragma unroll
        for (int n = 0; n < 7; ++n) {
            int co = coh * 128 + wm * 32 + m * 16 + rq;
            int xx = xh * 112 + wn * 56 + n * 8 + cq;
            float* p0 = out + ((size_t)co * H + y) * W + xx;
            float* p1 = out + ((size_t)(co + 8) * H + y) * W + xx;
            *(float2*)p0 = make_float2(acc[m][n][0], acc[m][n][1]);
            *(float2*)p1 = make_float2(acc[m][n][2], acc[m][n][3]);
        }
    }
}

extern "C" void kernel_launch(void* const* d_in, const int* in_sizes, int n_in,
                              void* d_out, int out_size) {
    const float* x = (const float*)d_in[0];   // [1,256,224,224]
    const float* w = (const float*)d_in[1];   // [256,256,3,3]
    float* out = (float*)d_out;               // [256,224,224]
    (void)in_sizes; (void)n_in; (void)out_size;

    prep_w_kernel<<<(WELEMS + 255) / 256, 256>>>(w);
    prep_x_kernel<<<dim3(226, 256), 224>>>(x);

    // grid.x: {xh, coh}; grid.y: output row y
    conv_mma_kernel<<<dim3(4, H), 256>>>(out);
}